// round 8
// baseline (speedup 1.0000x reference)
#include <cuda_runtime.h>
#include <cuda_bf16.h>
#include <cstdint>

#define B_ 8
#define C_ 32
#define H_ 256
#define W_ 512
#define D_ 48
#define HW_ ((size_t)(H_) * (W_))

#define WM 128                  // w per CTA (GEMM M)
#define NWT (W_ / WM)           // 4 tiles
#define NU (WM + D_)            // 176 B rows (band window)
#define NTH 256

// smem byte offsets. Operand rows: 32 bf16 = 64B data + 16B pad = 80B stride.
#define AROW 80
#define A_HI 0
#define A_LO (A_HI + WM * AROW)          // 10240
#define B_HI (A_LO + WM * AROW)          // 20480
#define B_LO (B_HI + NU * AROW)          // 34560
#define SMEM_BYTES (B_LO + NU * AROW)    // 48640

// bounce buffer (fp32), reuses operand region after compute: 128 rows x 66 floats
#define PROW 66

__device__ __forceinline__ void mma_bf16(float c[4],
                                         uint32_t a0, uint32_t a1, uint32_t a2, uint32_t a3,
                                         uint32_t b0, uint32_t b1) {
    asm volatile(
        "mma.sync.aligned.m16n8k16.row.col.f32.bf16.bf16.f32 "
        "{%0,%1,%2,%3}, {%4,%5,%6,%7}, {%8,%9}, {%0,%1,%2,%3};"
        : "+f"(c[0]), "+f"(c[1]), "+f"(c[2]), "+f"(c[3])
        : "r"(a0), "r"(a1), "r"(a2), "r"(a3), "r"(b0), "r"(b1));
}

__device__ __forceinline__ uint32_t lds32(const char* base, int byte_off) {
    return *reinterpret_cast<const uint32_t*>(base + byte_off);
}

__global__ __launch_bounds__(NTH, 3)
void corr_mma_kernel(const float* __restrict__ x,
                     const float* __restrict__ y,
                     float* __restrict__ out)
{
    extern __shared__ char smem[];

    const int tid  = threadIdx.x;
    const int wid  = tid >> 5;
    const int lane = tid & 31;
    const int g    = lane >> 2;     // 0..7
    const int t    = lane & 3;      // 0..3

    const int blk   = blockIdx.x;
    const int wtile = blk & (NWT - 1);
    const int bh    = blk >> 2;
    const int b     = bh / H_;
    const int h     = bh % H_;
    const int w0t   = wtile * WM;

    // ---- stage A: A[m][c] = x[c, w0t+m] split into bf16 hi/lo ----
    {
        const float* gx = x + ((size_t)(b * C_) * H_ + h) * W_ + w0t;
        #pragma unroll 4
        for (int i = tid; i < WM * C_; i += NTH) {
            int c = i >> 7;          // / 128
            int m = i & (WM - 1);
            float v = gx[(size_t)c * HW_ + m];
            __nv_bfloat16 hi = __float2bfloat16_rn(v);
            __nv_bfloat16 lo = __float2bfloat16_rn(v - __bfloat162float(hi));
            *reinterpret_cast<__nv_bfloat16*>(smem + A_HI + m * AROW + c * 2) = hi;
            *reinterpret_cast<__nv_bfloat16*>(smem + A_LO + m * AROW + c * 2) = lo;
        }
    }
    // ---- stage B: B[n][c] = y[c, w0t-48+n]; entries with u<0 are zero ----
    {
        const float* gy = y + ((size_t)(b * C_) * H_ + h) * W_;
        #pragma unroll 4
        for (int i = tid; i < NU * C_; i += NTH) {
            int c = i / NU;
            int n = i % NU;
            int u = w0t - D_ + n;
            float v = (u >= 0) ? gy[(size_t)c * HW_ + u] : 0.0f;
            __nv_bfloat16 hi = __float2bfloat16_rn(v);
            __nv_bfloat16 lo = __float2bfloat16_rn(v - __bfloat162float(hi));
            *reinterpret_cast<__nv_bfloat16*>(smem + B_HI + n * AROW + c * 2) = hi;
            *reinterpret_cast<__nv_bfloat16*>(smem + B_LO + n * AROW + c * 2) = lo;
        }
    }
    __syncthreads();

    // ---- banded mma: warp wid owns w rows [16*wid, 16*wid+16), u window 64 wide ----
    float acc[8][4];
    #pragma unroll
    for (int nt = 0; nt < 8; nt++)
        #pragma unroll
        for (int k = 0; k < 4; k++) acc[nt][k] = 0.f;

    {
        const int ar0 = 16 * wid + g;       // A row for a0/a2
        const int ar1 = ar0 + 8;            // A row for a1/a3
        #pragma unroll
        for (int k0 = 0; k0 < C_; k0 += 16) {
            const int kb = (k0 + 2 * t) * 2;       // byte offset of k pair
            uint32_t ah0 = lds32(smem, A_HI + ar0 * AROW + kb);
            uint32_t ah1 = lds32(smem, A_HI + ar1 * AROW + kb);
            uint32_t ah2 = lds32(smem, A_HI + ar0 * AROW + kb + 16);
            uint32_t ah3 = lds32(smem, A_HI + ar1 * AROW + kb + 16);
            uint32_t al0 = lds32(smem, A_LO + ar0 * AROW + kb);
            uint32_t al1 = lds32(smem, A_LO + ar1 * AROW + kb);
            uint32_t al2 = lds32(smem, A_LO + ar0 * AROW + kb + 16);
            uint32_t al3 = lds32(smem, A_LO + ar1 * AROW + kb + 16);
            #pragma unroll
            for (int nt = 0; nt < 8; nt++) {
                const int brow = 16 * wid + nt * 8 + g;
                uint32_t bh0 = lds32(smem, B_HI + brow * AROW + kb);
                uint32_t bh1 = lds32(smem, B_HI + brow * AROW + kb + 16);
                uint32_t bl0 = lds32(smem, B_LO + brow * AROW + kb);
                uint32_t bl1 = lds32(smem, B_LO + brow * AROW + kb + 16);
                mma_bf16(acc[nt], ah0, ah1, ah2, ah3, bh0, bh1);  // hi*hi
                mma_bf16(acc[nt], ah0, ah1, ah2, ah3, bl0, bl1);  // hi*lo
                mma_bf16(acc[nt], al0, al1, al2, al3, bh0, bh1);  // lo*hi
            }
        }
    }

    __syncthreads();   // operands fully consumed; reuse smem as bounce buffer

    // ---- write accumulators to bounce: P[w_local][col] ----
    {
        float* ps = reinterpret_cast<float*>(smem);
        #pragma unroll
        for (int nt = 0; nt < 8; nt++) {
            const int col = nt * 8 + 2 * t;
            float2 v01 = make_float2(acc[nt][0], acc[nt][1]);
            float2 v23 = make_float2(acc[nt][2], acc[nt][3]);
            *reinterpret_cast<float2*>(ps + (size_t)(16 * wid + g) * PROW + col) = v01;
            *reinterpret_cast<float2*>(ps + (size_t)(16 * wid + 8 + g) * PROW + col) = v23;
        }
    }
    __syncthreads();

    // ---- band extraction: out[w, d] = P[w_local][(w_local&15) + 48 - d] / C ----
    {
        const float inv = 1.0f / (float)C_;
        const float* ps = reinterpret_cast<const float*>(smem);
        const int wl   = tid & (WM - 1);
        const int half = tid >> 7;             // 0: d 0..23, 1: d 24..47
        const float* psrow = ps + (size_t)wl * PROW + (wl & 15) + D_;
        float* op = out + ((size_t)(b * D_ + half * 24) * H_ + h) * W_ + w0t + wl;
        #pragma unroll
        for (int dd = 0; dd < 24; dd++) {
            int d = half * 24 + dd;
            op[(size_t)dd * HW_] = psrow[-d] * inv;
        }
    }
}

extern "C" void kernel_launch(void* const* d_in, const int* in_sizes, int n_in,
                              void* d_out, int out_size)
{
    const float* x = (const float*)d_in[0];
    const float* y = (const float*)d_in[1];
    float* out = (float*)d_out;

    static bool attr_set = false;
    if (!attr_set) {
        cudaFuncSetAttribute(corr_mma_kernel,
                             cudaFuncAttributeMaxDynamicSharedMemorySize,
                             SMEM_BYTES);
        attr_set = true;
    }

    corr_mma_kernel<<<B_ * H_ * NWT, NTH, SMEM_BYTES>>>(x, y, out);
}

// round 9
// speedup vs baseline: 1.2445x; 1.2445x over previous
#include <cuda_runtime.h>
#include <cuda_bf16.h>
#include <cstdint>

#define B_ 8
#define C_ 32
#define H_ 256
#define W_ 512
#define D_ 48
#define HW_ ((size_t)(H_) * (W_))

#define WM 128                  // w per CTA (GEMM M)
#define NWT (W_ / WM)           // 4 tiles
#define NU (WM + D_)            // 176 B rows (band window)
#define NTH 256

// smem byte offsets. Operand rows: 32 bf16 = 64B data + 16B pad = 80B stride.
#define AROW 80
#define A_HI 0
#define A_LO (A_HI + WM * AROW)          // 10240
#define B_HI (A_LO + WM * AROW)          // 20480
#define B_LO (B_HI + NU * AROW)          // 34560
#define SMEM_BYTES (B_LO + NU * AROW)    // 48640

// bounce buffer (fp32), reuses operand region after compute: 128 rows x 66 floats
#define PROW 66

__device__ __forceinline__ void mma_bf16(float c[4],
                                         uint32_t a0, uint32_t a1, uint32_t a2, uint32_t a3,
                                         uint32_t b0, uint32_t b1) {
    asm volatile(
        "mma.sync.aligned.m16n8k16.row.col.f32.bf16.bf16.f32 "
        "{%0,%1,%2,%3}, {%4,%5,%6,%7}, {%8,%9}, {%0,%1,%2,%3};"
        : "+f"(c[0]), "+f"(c[1]), "+f"(c[2]), "+f"(c[3])
        : "r"(a0), "r"(a1), "r"(a2), "r"(a3), "r"(b0), "r"(b1));
}

#define LDSM_X4(r0, r1, r2, r3, addr)                                         \
    asm volatile("ldmatrix.sync.aligned.m8n8.x4.shared.b16 {%0,%1,%2,%3}, [%4];" \
                 : "=r"(r0), "=r"(r1), "=r"(r2), "=r"(r3) : "r"(addr))
#define LDSM_X2(r0, r1, addr)                                                 \
    asm volatile("ldmatrix.sync.aligned.m8n8.x2.shared.b16 {%0,%1}, [%2];"    \
                 : "=r"(r0), "=r"(r1) : "r"(addr))

// split v[0..3] (one row, 4 consecutive c) into bf16 hi/lo pairs, store 8B each
__device__ __forceinline__ void split_store(char* smem, int row, int cq,
                                            const float v[4]) {
    uint32_t hi01, hi23, lo01, lo23;
    asm("cvt.rn.bf16x2.f32 %0, %1, %2;" : "=r"(hi01) : "f"(v[1]), "f"(v[0]));
    asm("cvt.rn.bf16x2.f32 %0, %1, %2;" : "=r"(hi23) : "f"(v[3]), "f"(v[2]));
    float h0 = __uint_as_float(hi01 << 16);
    float h1 = __uint_as_float(hi01 & 0xFFFF0000u);
    float h2 = __uint_as_float(hi23 << 16);
    float h3 = __uint_as_float(hi23 & 0xFFFF0000u);
    float l0 = v[0] - h0, l1 = v[1] - h1, l2 = v[2] - h2, l3 = v[3] - h3;
    asm("cvt.rn.bf16x2.f32 %0, %1, %2;" : "=r"(lo01) : "f"(l1), "f"(l0));
    asm("cvt.rn.bf16x2.f32 %0, %1, %2;" : "=r"(lo23) : "f"(l3), "f"(l2));
    *reinterpret_cast<uint2*>(smem + row * AROW + cq * 8) = make_uint2(hi01, hi23);
    *reinterpret_cast<uint2*>(smem + (WM * AROW) + row * AROW + cq * 8) =
        make_uint2(lo01, lo23);   // LO region sits exactly WM*AROW after HI (A); see note below
}

__global__ __launch_bounds__(NTH, 3)
void corr_mma_kernel(const float* __restrict__ x,
                     const float* __restrict__ y,
                     float* __restrict__ out)
{
    extern __shared__ char smem[];
    const uint32_t sbase = (uint32_t)__cvta_generic_to_shared(smem);

    const int tid  = threadIdx.x;
    const int wid  = tid >> 5;
    const int lane = tid & 31;
    const int g    = lane >> 2;
    const int t    = lane & 3;

    const int blk   = blockIdx.x;
    const int wtile = blk & (NWT - 1);
    const int bh    = blk >> 2;
    const int b     = bh / H_;
    const int h     = bh % H_;
    const int w0t   = wtile * WM;

    const float* gx = x + ((size_t)(b * C_) * H_ + h) * W_ + w0t;
    const float* gy = y + ((size_t)(b * C_) * H_ + h) * W_ + w0t;

    // ---- staging: all global loads issued up front (high MLP), then convert ----
    // A units: u = tid + k*256, m = u&127, cq = u>>7; load x[4cq..4cq+3][w0t+m]
    float va[4][4];
    #pragma unroll
    for (int k = 0; k < 4; k++) {
        int u = tid + k * NTH;
        int m = u & (WM - 1), cq = u >> 7;
        const float* p = gx + (size_t)(4 * cq) * HW_ + m;
        va[k][0] = p[0]; va[k][1] = p[HW_]; va[k][2] = p[2 * HW_]; va[k][3] = p[3 * HW_];
    }
    // B main units: rows n = 48 + (u&127); global col w0t + (u&127)  (always in range)
    float vb[4][4];
    #pragma unroll
    for (int k = 0; k < 4; k++) {
        int u = tid + k * NTH;
        int j = u & (WM - 1), cq = u >> 7;
        const float* p = gy + (size_t)(4 * cq) * HW_ + j;
        vb[k][0] = p[0]; vb[k][1] = p[HW_]; vb[k][2] = p[2 * HW_]; vb[k][3] = p[3 * HW_];
    }
    // B halo units: u in [0,384), rows n = u%48, cq = u/48; global col w0t-48+n
    float vh[2][4];
    #pragma unroll
    for (int k = 0; k < 2; k++) {
        int u = tid + k * NTH;
        vh[k][0] = vh[k][1] = vh[k][2] = vh[k][3] = 0.f;
        if (u < 48 * 8) {
            int n = u % 48, cq = u / 48;
            int gcol = n - D_;                    // relative to gy (col w0t)
            if (w0t + gcol >= 0) {
                const float* p = gy + (size_t)(4 * cq) * HW_ + gcol;
                vh[k][0] = p[0]; vh[k][1] = p[HW_]; vh[k][2] = p[2 * HW_]; vh[k][3] = p[3 * HW_];
            }
        }
    }
    // convert + store (HI/LO regions are both WM*AROW or NU*AROW apart; note:
    // A_LO-A_HI = WM*AROW and B_LO-B_HI = NU*AROW, so pass region-specific base)
    #pragma unroll
    for (int k = 0; k < 4; k++) {
        int u = tid + k * NTH;
        int m = u & (WM - 1), cq = u >> 7;
        // A: HI at A_HI, LO at A_HI + WM*AROW  (= A_LO)  ✓ matches split_store
        split_store(smem + A_HI, m, cq, va[k]);
    }
    #pragma unroll
    for (int k = 0; k < 4; k++) {
        int u = tid + k * NTH;
        int n = 48 + (u & (WM - 1)), cq = u >> 7;
        // B: HI at B_HI, LO at B_HI + NU*AROW (= B_LO): store manually since spacing differs
        uint32_t hi01, hi23, lo01, lo23;
        const float* v = vb[k];
        asm("cvt.rn.bf16x2.f32 %0, %1, %2;" : "=r"(hi01) : "f"(v[1]), "f"(v[0]));
        asm("cvt.rn.bf16x2.f32 %0, %1, %2;" : "=r"(hi23) : "f"(v[3]), "f"(v[2]));
        float h0 = __uint_as_float(hi01 << 16), h1 = __uint_as_float(hi01 & 0xFFFF0000u);
        float h2 = __uint_as_float(hi23 << 16), h3 = __uint_as_float(hi23 & 0xFFFF0000u);
        float l0 = v[0] - h0, l1 = v[1] - h1, l2 = v[2] - h2, l3 = v[3] - h3;
        asm("cvt.rn.bf16x2.f32 %0, %1, %2;" : "=r"(lo01) : "f"(l1), "f"(l0));
        asm("cvt.rn.bf16x2.f32 %0, %1, %2;" : "=r"(lo23) : "f"(l3), "f"(l2));
        *reinterpret_cast<uint2*>(smem + B_HI + n * AROW + cq * 8) = make_uint2(hi01, hi23);
        *reinterpret_cast<uint2*>(smem + B_LO + n * AROW + cq * 8) = make_uint2(lo01, lo23);
    }
    #pragma unroll
    for (int k = 0; k < 2; k++) {
        int u = tid + k * NTH;
        if (u < 48 * 8) {
            int n = u % 48, cq = u / 48;
            uint32_t hi01, hi23, lo01, lo23;
            const float* v = vh[k];
            asm("cvt.rn.bf16x2.f32 %0, %1, %2;" : "=r"(hi01) : "f"(v[1]), "f"(v[0]));
            asm("cvt.rn.bf16x2.f32 %0, %1, %2;" : "=r"(hi23) : "f"(v[3]), "f"(v[2]));
            float h0 = __uint_as_float(hi01 << 16), h1 = __uint_as_float(hi01 & 0xFFFF0000u);
            float h2 = __uint_as_float(hi23 << 16), h3 = __uint_as_float(hi23 & 0xFFFF0000u);
            float l0 = v[0] - h0, l1 = v[1] - h1, l2 = v[2] - h2, l3 = v[3] - h3;
            asm("cvt.rn.bf16x2.f32 %0, %1, %2;" : "=r"(lo01) : "f"(l1), "f"(l0));
            asm("cvt.rn.bf16x2.f32 %0, %1, %2;" : "=r"(lo23) : "f"(l3), "f"(l2));
            *reinterpret_cast<uint2*>(smem + B_HI + n * AROW + cq * 8) = make_uint2(hi01, hi23);
            *reinterpret_cast<uint2*>(smem + B_LO + n * AROW + cq * 8) = make_uint2(lo01, lo23);
        }
    }
    __syncthreads();

    // ---- banded mma via ldmatrix: warp wid owns w rows [16wid,16wid+16) ----
    float acc[8][4];
    #pragma unroll
    for (int nt = 0; nt < 8; nt++)
        #pragma unroll
        for (int k = 0; k < 4; k++) acc[nt][k] = 0.f;

    {
        // A x4: lane -> row 16wid + (lane&15), byte col (lane>>4)*16
        const uint32_t a_addr = sbase + A_HI +
            (16 * wid + (lane & 15)) * AROW + ((lane >> 4) * 16);
        // B x2: lanes 0-15 -> row 16wid + (lane&7), byte col ((lane>>3)&1)*16
        const uint32_t b_addr = sbase + B_HI +
            (16 * wid + (lane & 7)) * AROW + (((lane >> 3) & 1) * 16);

        #pragma unroll
        for (int k0 = 0; k0 < 2; k0++) {
            const uint32_t koff = k0 * 32;          // 16 k-elems * 2B
            uint32_t ah[4], al[4];
            LDSM_X4(ah[0], ah[1], ah[2], ah[3], a_addr + koff);
            LDSM_X4(al[0], al[1], al[2], al[3], a_addr + (A_LO - A_HI) + koff);
            #pragma unroll
            for (int nt = 0; nt < 8; nt++) {
                uint32_t bh[2], bl[2];
                LDSM_X2(bh[0], bh[1], b_addr + nt * 8 * AROW + koff);
                LDSM_X2(bl[0], bl[1], b_addr + (B_LO - B_HI) + nt * 8 * AROW + koff);
                mma_bf16(acc[nt], ah[0], ah[1], ah[2], ah[3], bh[0], bh[1]); // hi*hi
                mma_bf16(acc[nt], ah[0], ah[1], ah[2], ah[3], bl[0], bl[1]); // hi*lo
                mma_bf16(acc[nt], al[0], al[1], al[2], al[3], bh[0], bh[1]); // lo*hi
            }
        }
    }

    __syncthreads();   // operands consumed; reuse smem as bounce buffer

    // ---- write accumulators to bounce: P[w_local][col] ----
    {
        float* ps = reinterpret_cast<float*>(smem);
        #pragma unroll
        for (int nt = 0; nt < 8; nt++) {
            const int col = nt * 8 + 2 * t;
            float2 v01 = make_float2(acc[nt][0], acc[nt][1]);
            float2 v23 = make_float2(acc[nt][2], acc[nt][3]);
            *reinterpret_cast<float2*>(ps + (size_t)(16 * wid + g) * PROW + col) = v01;
            *reinterpret_cast<float2*>(ps + (size_t)(16 * wid + 8 + g) * PROW + col) = v23;
        }
    }
    __syncthreads();

    // ---- band extraction: out[w, d] = P[w_local][(w_local&15) + 48 - d] / C ----
    {
        const float inv = 1.0f / (float)C_;
        const float* ps = reinterpret_cast<const float*>(smem);
        const int wl   = tid & (WM - 1);
        const int half = tid >> 7;
        const float* psrow = ps + (size_t)wl * PROW + (wl & 15) + D_;
        float* op = out + ((size_t)(b * D_ + half * 24) * H_ + h) * W_ + w0t + wl;
        #pragma unroll
        for (int dd = 0; dd < 24; dd++) {
            int d = half * 24 + dd;
            op[(size_t)dd * HW_] = psrow[-d] * inv;
        }
    }
}

extern "C" void kernel_launch(void* const* d_in, const int* in_sizes, int n_in,
                              void* d_out, int out_size)
{
    const float* x = (const float*)d_in[0];
    const float* y = (const float*)d_in[1];
    float* out = (float*)d_out;

    static bool attr_set = false;
    if (!attr_set) {
        cudaFuncSetAttribute(corr_mma_kernel,
                             cudaFuncAttributeMaxDynamicSharedMemorySize,
                             SMEM_BYTES);
        attr_set = true;
    }

    corr_mma_kernel<<<B_ * H_ * NWT, NTH, SMEM_BYTES>>>(x, y, out);
}

// round 13
// speedup vs baseline: 1.8903x; 1.5190x over previous
#include <cuda_runtime.h>
#include <cuda_bf16.h>
#include <cstdint>

#define B_ 8
#define C_ 32
#define H_ 256
#define W_ 512
#define D_ 48
#define HW_ ((size_t)(H_) * (W_))

#define WM 128                  // w per CTA (GEMM M)
#define NWT (W_ / WM)           // 4 tiles
#define NU (WM + D_)            // 176 B rows (band window)
#define NTH 256

// granule-major operand layout: addr = REGION + (cq2 * ROWS + row) * 16
// (granule = 16B = 8 bf16 = 8 consecutive c; cq2 in [0,4))
#define A_HI 0
#define A_LO (A_HI + 4 * WM * 16)        // 8192
#define B_HI (A_LO + 4 * WM * 16)        // 16384
#define B_LO (B_HI + 4 * NU * 16)        // 27648
#define SMEM_BYTES (B_LO + 4 * NU * 16)  // 38912

// bounce buffer (fp32): 128 rows x 66 floats = 33792 B <= SMEM_BYTES
#define PROW 66

__device__ __forceinline__ void mma_bf16(float c[4],
                                         uint32_t a0, uint32_t a1, uint32_t a2, uint32_t a3,
                                         uint32_t b0, uint32_t b1) {
    asm volatile(
        "mma.sync.aligned.m16n8k16.row.col.f32.bf16.bf16.f32 "
        "{%0,%1,%2,%3}, {%4,%5,%6,%7}, {%8,%9}, {%0,%1,%2,%3};"
        : "+f"(c[0]), "+f"(c[1]), "+f"(c[2]), "+f"(c[3])
        : "r"(a0), "r"(a1), "r"(a2), "r"(a3), "r"(b0), "r"(b1));
}

#define LDSM_X4(r0, r1, r2, r3, addr)                                            \
    asm volatile("ldmatrix.sync.aligned.m8n8.x4.shared.b16 {%0,%1,%2,%3}, [%4];" \
                 : "=r"(r0), "=r"(r1), "=r"(r2), "=r"(r3) : "r"(addr))

// convert 8 fp32 -> bf16 hi granule + lo granule
__device__ __forceinline__ void cvt8(const float* v, uint4& hi, uint4& lo) {
    uint32_t hh[4], ll[4];
    #pragma unroll
    for (int i = 0; i < 4; i++) {
        asm("cvt.rn.bf16x2.f32 %0, %1, %2;" : "=r"(hh[i]) : "f"(v[2*i+1]), "f"(v[2*i]));
        float e0 = v[2*i]     - __uint_as_float(hh[i] << 16);
        float e1 = v[2*i + 1] - __uint_as_float(hh[i] & 0xFFFF0000u);
        asm("cvt.rn.bf16x2.f32 %0, %1, %2;" : "=r"(ll[i]) : "f"(e1), "f"(e0));
    }
    hi = make_uint4(hh[0], hh[1], hh[2], hh[3]);
    lo = make_uint4(ll[0], ll[1], ll[2], ll[3]);
}

__global__ __launch_bounds__(NTH, 3)
void corr_mma_kernel(const float* __restrict__ x,
                     const float* __restrict__ y,
                     float* __restrict__ out)
{
    extern __shared__ char smem[];
    const uint32_t sbase = (uint32_t)__cvta_generic_to_shared(smem);

    const int tid  = threadIdx.x;
    const int wid  = tid >> 5;
    const int lane = tid & 31;
    const int g    = lane >> 2;
    const int t    = lane & 3;

    const int blk   = blockIdx.x;
    const int wtile = blk & (NWT - 1);
    const int bh    = blk >> 2;
    const int b     = bh / H_;
    const int h     = bh % H_;
    const int w0t   = wtile * WM;

    const float* gx = x + ((size_t)(b * C_) * H_ + h) * W_ + w0t;
    const float* gy = y + ((size_t)(b * C_) * H_ + h) * W_ + w0t;

    // ---- staging: 5 units of 8 coalesced LDG each, double-buffered ----
    // units 0,1: A (u = tid + it*256: m = u&127, cq2 = u>>7)
    // units 2,3: B main (j = u&127 -> n = 48+j)
    // unit 4:    B halo (tid<192: n = tid%48, cq2 = tid/48)
    auto load_A = [&](int it, float* v) {
        int u = tid + it * NTH;
        int m = u & (WM - 1), cq2 = u >> 7;
        const float* p = gx + (size_t)(cq2 * 8) * HW_ + m;
        #pragma unroll
        for (int j = 0; j < 8; j++) v[j] = p[(size_t)j * HW_];
    };
    auto store_A = [&](int it, const float* v) {
        int u = tid + it * NTH;
        int m = u & (WM - 1), cq2 = u >> 7;
        uint4 hi, lo; cvt8(v, hi, lo);
        int goff = (cq2 * WM + m) * 16;
        *reinterpret_cast<uint4*>(smem + A_HI + goff) = hi;
        *reinterpret_cast<uint4*>(smem + A_LO + goff) = lo;
    };
    auto load_Bm = [&](int it, float* v) {
        int u = tid + it * NTH;
        int j = u & (WM - 1), cq2 = u >> 7;
        const float* p = gy + (size_t)(cq2 * 8) * HW_ + j;
        #pragma unroll
        for (int k = 0; k < 8; k++) v[k] = p[(size_t)k * HW_];
    };
    auto store_Bm = [&](int it, const float* v) {
        int u = tid + it * NTH;
        int j = u & (WM - 1), cq2 = u >> 7;
        int n = 48 + j;
        uint4 hi, lo; cvt8(v, hi, lo);
        int goff = (cq2 * NU + n) * 16;
        *reinterpret_cast<uint4*>(smem + B_HI + goff) = hi;
        *reinterpret_cast<uint4*>(smem + B_LO + goff) = lo;
    };
    auto load_Bh = [&](float* v) {
        #pragma unroll
        for (int k = 0; k < 8; k++) v[k] = 0.f;
        if (tid < 48 * 4) {
            int n = tid % 48, cq2 = tid / 48;
            int gcol = n - D_;
            if (w0t + gcol >= 0) {
                const float* p = gy + (size_t)(cq2 * 8) * HW_ + gcol;
                #pragma unroll
                for (int k = 0; k < 8; k++) v[k] = p[(size_t)k * HW_];
            }
        }
    };
    auto store_Bh = [&](const float* v) {
        if (tid < 48 * 4) {
            int n = tid % 48, cq2 = tid / 48;
            uint4 hi, lo; cvt8(v, hi, lo);
            int goff = (cq2 * NU + n) * 16;
            *reinterpret_cast<uint4*>(smem + B_HI + goff) = hi;
            *reinterpret_cast<uint4*>(smem + B_LO + goff) = lo;
        }
    };

    {
        float b0[8], b1[8];
        load_A(0, b0);
        load_A(1, b1);
        store_A(0, b0);
        load_Bm(0, b0);
        store_A(1, b1);
        load_Bm(1, b1);
        store_Bm(0, b0);
        load_Bh(b0);
        store_Bm(1, b1);
        store_Bh(b0);
    }
    __syncthreads();

    // ---- banded mma via ldmatrix.x4: warp wid owns w rows [16wid,16wid+16) ----
    float acc[8][4];
    #pragma unroll
    for (int nt = 0; nt < 8; nt++)
        #pragma unroll
        for (int k = 0; k < 4; k++) acc[nt][k] = 0.f;

    {
        // A: lane -> row 16wid + (lane&15), k-half = lane>>4
        const int ar   = 16 * wid + (lane & 15);
        const int ksel = lane >> 4;
        // B: lane -> r = lane&7, mi = lane>>3; matrices (b0,b1) of nt=2nt2, then nt=2nt2+1
        const int br_r     = lane & 7;
        const int b_half   = (lane >> 3) & 1;
        const int b_rowoff = (lane >> 4) * 8;

        #pragma unroll
        for (int k0 = 0; k0 < 2; k0++) {
            uint32_t a_addr = sbase + A_HI + (((k0 * 2 + ksel) * WM) + ar) * 16;
            uint32_t ah[4], al[4];
            LDSM_X4(ah[0], ah[1], ah[2], ah[3], a_addr);
            LDSM_X4(al[0], al[1], al[2], al[3], a_addr + (A_LO - A_HI));
            #pragma unroll
            for (int nt2 = 0; nt2 < 4; nt2++) {
                const int brow = 16 * wid + nt2 * 16 + b_rowoff + br_r;
                uint32_t b_addr = sbase + B_HI +
                    (((k0 * 2 + b_half) * NU) + brow) * 16;
                uint32_t bhf[4], blf[4];
                LDSM_X4(bhf[0], bhf[1], bhf[2], bhf[3], b_addr);
                LDSM_X4(blf[0], blf[1], blf[2], blf[3], b_addr + (B_LO - B_HI));
                float* a0 = acc[2 * nt2];
                float* a1 = acc[2 * nt2 + 1];
                mma_bf16(a0, ah[0], ah[1], ah[2], ah[3], bhf[0], bhf[1]); // hi*hi
                mma_bf16(a0, ah[0], ah[1], ah[2], ah[3], blf[0], blf[1]); // hi*lo
                mma_bf16(a0, al[0], al[1], al[2], al[3], bhf[0], bhf[1]); // lo*hi
                mma_bf16(a1, ah[0], ah[1], ah[2], ah[3], bhf[2], bhf[3]);
                mma_bf16(a1, ah[0], ah[1], ah[2], ah[3], blf[2], blf[3]);
                mma_bf16(a1, al[0], al[1], al[2], al[3], bhf[2], bhf[3]);
            }
        }
    }

    __syncthreads();   // operands consumed; reuse smem as bounce buffer

    // ---- write accumulators to bounce: P[w_local][col] ----
    {
        float* ps = reinterpret_cast<float*>(smem);
        #pragma unroll
        for (int nt = 0; nt < 8; nt++) {
            const int col = nt * 8 + 2 * t;
            float2 v01 = make_float2(acc[nt][0], acc[nt][1]);
            float2 v23 = make_float2(acc[nt][2], acc[nt][3]);
            *reinterpret_cast<float2*>(ps + (size_t)(16 * wid + g) * PROW + col) = v01;
            *reinterpret_cast<float2*>(ps + (size_t)(16 * wid + 8 + g) * PROW + col) = v23;
        }
    }
    __syncthreads();

    // ---- band extraction: out[w, d] = P[w_local][(w_local&15) + 48 - d] / C ----
    {
        const float inv = 1.0f / (float)C_;
        const float* ps = reinterpret_cast<const float*>(smem);
        const int wl   = tid & (WM - 1);
        const int half = tid >> 7;
        const float* psrow = ps + (size_t)wl * PROW + (wl & 15) + D_;
        float* op = out + ((size_t)(b * D_ + half * 24) * H_ + h) * W_ + w0t + wl;
        #pragma unroll
        for (int dd = 0; dd < 24; dd++) {
            int d = half * 24 + dd;
            op[(size_t)dd * HW_] = psrow[-d] * inv;
        }
    }
}

extern "C" void kernel_launch(void* const* d_in, const int* in_sizes, int n_in,
                              void* d_out, int out_size)
{
    const float* x = (const float*)d_in[0];
    const float* y = (const float*)d_in[1];
    float* out = (float*)d_out;

    static bool attr_set = false;
    if (!attr_set) {
        cudaFuncSetAttribute(corr_mma_kernel,
                             cudaFuncAttributeMaxDynamicSharedMemorySize,
                             SMEM_BYTES);
        attr_set = true;
    }

    corr_mma_kernel<<<B_ * H_ * NWT, NTH, SMEM_BYTES>>>(x, y, out);
}

// round 14
// speedup vs baseline: 2.3931x; 1.2660x over previous
#include <cuda_runtime.h>
#include <cuda_bf16.h>
#include <cstdint>

#define B_ 8
#define C_ 32
#define H_ 256
#define W_ 512
#define D_ 48
#define HW_ ((size_t)(H_) * (W_))

#define WM 128                  // w per CTA (GEMM M)
#define NWT (W_ / WM)           // 4 tiles
#define NU (WM + D_)            // 176 B rows (band window)
#define NTH 256

// granule-major operand layout: addr = REGION + (cq2 * ROWS + row) * 16
#define A_HI 0
#define A_LO (A_HI + 4 * WM * 16)        // 8192
#define B_HI (A_LO + 4 * WM * 16)        // 16384
#define B_LO (B_HI + 4 * NU * 16)        // 27648
#define SMEM_BYTES (B_LO + 4 * NU * 16)  // 38912

// bounce buffer (fp32), COLUMN-major: addr = col * CSTRIDE + row
// 64 cols x 132 stride x 4B = 33792 B <= SMEM_BYTES
#define CSTRIDE 132

__device__ __forceinline__ void mma_bf16(float c[4],
                                         uint32_t a0, uint32_t a1, uint32_t a2, uint32_t a3,
                                         uint32_t b0, uint32_t b1) {
    asm volatile(
        "mma.sync.aligned.m16n8k16.row.col.f32.bf16.bf16.f32 "
        "{%0,%1,%2,%3}, {%4,%5,%6,%7}, {%8,%9}, {%0,%1,%2,%3};"
        : "+f"(c[0]), "+f"(c[1]), "+f"(c[2]), "+f"(c[3])
        : "r"(a0), "r"(a1), "r"(a2), "r"(a3), "r"(b0), "r"(b1));
}

#define LDSM_X4(r0, r1, r2, r3, addr)                                            \
    asm volatile("ldmatrix.sync.aligned.m8n8.x4.shared.b16 {%0,%1,%2,%3}, [%4];" \
                 : "=r"(r0), "=r"(r1), "=r"(r2), "=r"(r3) : "r"(addr))

// convert 8 fp32 -> bf16 hi granule + lo granule
__device__ __forceinline__ void cvt8(const float* v, uint4& hi, uint4& lo) {
    uint32_t hh[4], ll[4];
    #pragma unroll
    for (int i = 0; i < 4; i++) {
        asm("cvt.rn.bf16x2.f32 %0, %1, %2;" : "=r"(hh[i]) : "f"(v[2*i+1]), "f"(v[2*i]));
        float e0 = v[2*i]     - __uint_as_float(hh[i] << 16);
        float e1 = v[2*i + 1] - __uint_as_float(hh[i] & 0xFFFF0000u);
        asm("cvt.rn.bf16x2.f32 %0, %1, %2;" : "=r"(ll[i]) : "f"(e1), "f"(e0));
    }
    hi = make_uint4(hh[0], hh[1], hh[2], hh[3]);
    lo = make_uint4(ll[0], ll[1], ll[2], ll[3]);
}

__global__ __launch_bounds__(NTH, 4)
void corr_mma_kernel(const float* __restrict__ x,
                     const float* __restrict__ y,
                     float* __restrict__ out)
{
    extern __shared__ char smem[];
    const uint32_t sbase = (uint32_t)__cvta_generic_to_shared(smem);

    const int tid  = threadIdx.x;
    const int wid  = tid >> 5;
    const int lane = tid & 31;
    const int g    = lane >> 2;
    const int t    = lane & 3;

    const int blk   = blockIdx.x;
    const int wtile = blk & (NWT - 1);
    const int bh    = blk >> 2;
    const int b     = bh / H_;
    const int h     = bh % H_;
    const int w0t   = wtile * WM;

    const float* gx = x + ((size_t)(b * C_) * H_ + h) * W_ + w0t;
    const float* gy = y + ((size_t)(b * C_) * H_ + h) * W_ + w0t;

    // ---- staging: 5 units of 8 coalesced LDG each, double-buffered ----
    auto load_A = [&](int it, float* v) {
        int u = tid + it * NTH;
        int m = u & (WM - 1), cq2 = u >> 7;
        const float* p = gx + (size_t)(cq2 * 8) * HW_ + m;
        #pragma unroll
        for (int j = 0; j < 8; j++) v[j] = p[(size_t)j * HW_];
    };
    auto store_A = [&](int it, const float* v) {
        int u = tid + it * NTH;
        int m = u & (WM - 1), cq2 = u >> 7;
        uint4 hi, lo; cvt8(v, hi, lo);
        int goff = (cq2 * WM + m) * 16;
        *reinterpret_cast<uint4*>(smem + A_HI + goff) = hi;
        *reinterpret_cast<uint4*>(smem + A_LO + goff) = lo;
    };
    auto load_Bm = [&](int it, float* v) {
        int u = tid + it * NTH;
        int j = u & (WM - 1), cq2 = u >> 7;
        const float* p = gy + (size_t)(cq2 * 8) * HW_ + j;
        #pragma unroll
        for (int k = 0; k < 8; k++) v[k] = p[(size_t)k * HW_];
    };
    auto store_Bm = [&](int it, const float* v) {
        int u = tid + it * NTH;
        int j = u & (WM - 1), cq2 = u >> 7;
        int n = 48 + j;
        uint4 hi, lo; cvt8(v, hi, lo);
        int goff = (cq2 * NU + n) * 16;
        *reinterpret_cast<uint4*>(smem + B_HI + goff) = hi;
        *reinterpret_cast<uint4*>(smem + B_LO + goff) = lo;
    };
    auto load_Bh = [&](float* v) {
        #pragma unroll
        for (int k = 0; k < 8; k++) v[k] = 0.f;
        if (tid < 48 * 4) {
            int n = tid % 48, cq2 = tid / 48;
            int gcol = n - D_;
            if (w0t + gcol >= 0) {
                const float* p = gy + (size_t)(cq2 * 8) * HW_ + gcol;
                #pragma unroll
                for (int k = 0; k < 8; k++) v[k] = p[(size_t)k * HW_];
            }
        }
    };
    auto store_Bh = [&](const float* v) {
        if (tid < 48 * 4) {
            int n = tid % 48, cq2 = tid / 48;
            uint4 hi, lo; cvt8(v, hi, lo);
            int goff = (cq2 * NU + n) * 16;
            *reinterpret_cast<uint4*>(smem + B_HI + goff) = hi;
            *reinterpret_cast<uint4*>(smem + B_LO + goff) = lo;
        }
    };

    {
        float b0[8], b1[8];
        load_A(0, b0);
        load_A(1, b1);
        store_A(0, b0);
        load_Bm(0, b0);
        store_A(1, b1);
        load_Bm(1, b1);
        store_Bm(0, b0);
        load_Bh(b0);
        store_Bm(1, b1);
        store_Bh(b0);
    }
    __syncthreads();

    // ---- banded mma via ldmatrix.x4: warp wid owns w rows [16wid,16wid+16) ----
    float acc[8][4];
    #pragma unroll
    for (int nt = 0; nt < 8; nt++)
        #pragma unroll
        for (int k = 0; k < 4; k++) acc[nt][k] = 0.f;

    {
        const int ar   = 16 * wid + (lane & 15);
        const int ksel = lane >> 4;
        const int br_r     = lane & 7;
        const int b_half   = (lane >> 3) & 1;
        const int b_rowoff = (lane >> 4) * 8;

        #pragma unroll
        for (int k0 = 0; k0 < 2; k0++) {
            uint32_t a_addr = sbase + A_HI + (((k0 * 2 + ksel) * WM) + ar) * 16;
            uint32_t ah[4], al[4];
            LDSM_X4(ah[0], ah[1], ah[2], ah[3], a_addr);
            LDSM_X4(al[0], al[1], al[2], al[3], a_addr + (A_LO - A_HI));
            #pragma unroll
            for (int nt2 = 0; nt2 < 4; nt2++) {
                const int brow = 16 * wid + nt2 * 16 + b_rowoff + br_r;
                uint32_t b_addr = sbase + B_HI +
                    (((k0 * 2 + b_half) * NU) + brow) * 16;
                uint32_t bhf[4], blf[4];
                LDSM_X4(bhf[0], bhf[1], bhf[2], bhf[3], b_addr);
                LDSM_X4(blf[0], blf[1], blf[2], blf[3], b_addr + (B_LO - B_HI));
                float* a0 = acc[2 * nt2];
                float* a1 = acc[2 * nt2 + 1];
                mma_bf16(a0, ah[0], ah[1], ah[2], ah[3], bhf[0], bhf[1]); // hi*hi
                mma_bf16(a0, ah[0], ah[1], ah[2], ah[3], blf[0], blf[1]); // hi*lo
                mma_bf16(a0, al[0], al[1], al[2], al[3], bhf[0], bhf[1]); // lo*hi
                mma_bf16(a1, ah[0], ah[1], ah[2], ah[3], bhf[2], bhf[3]);
                mma_bf16(a1, ah[0], ah[1], ah[2], ah[3], blf[2], blf[3]);
                mma_bf16(a1, al[0], al[1], al[2], al[3], bhf[2], bhf[3]);
            }
        }
    }

    __syncthreads();   // operands consumed; reuse smem as bounce buffer

    // ---- bounce store, COLUMN-major: ps[col*CSTRIDE + row] ----
    // banks per instr: 4*(8nt+2t) + 16wid + g ≡ 8t + g + const (mod 32): conflict-free
    {
        float* ps = reinterpret_cast<float*>(smem);
        const int r0 = 16 * wid + g;
        const int r1 = r0 + 8;
        #pragma unroll
        for (int nt = 0; nt < 8; nt++) {
            const int c = nt * 8 + 2 * t;
            ps[(c)     * CSTRIDE + r0] = acc[nt][0];
            ps[(c + 1) * CSTRIDE + r0] = acc[nt][1];
            ps[(c)     * CSTRIDE + r1] = acc[nt][2];
            ps[(c + 1) * CSTRIDE + r1] = acc[nt][3];
        }
    }
    __syncthreads();

    // ---- band extraction: out[w, d] = P[w_local][(w_local&15) + 48 - d] / C ----
    // read addr = c*CSTRIDE + wl -> bank ≡ 5*wl (mod 32): conflict-free
    {
        const float inv = 1.0f / (float)C_;
        const float* ps = reinterpret_cast<const float*>(smem);
        const int wl   = tid & (WM - 1);
        const int half = tid >> 7;             // 0: d 0..23, 1: d 24..47
        const int c0   = (wl & 15) + D_ - half * 24;   // col for dd=0
        const float* p = ps + (size_t)c0 * CSTRIDE + wl;
        float* op = out + ((size_t)(b * D_ + half * 24) * H_ + h) * W_ + w0t + wl;
        #pragma unroll
        for (int dd = 0; dd < 24; dd++) {
            op[(size_t)dd * HW_] = p[-(size_t)dd * CSTRIDE] * inv;
        }
    }
}

extern "C" void kernel_launch(void* const* d_in, const int* in_sizes, int n_in,
                              void* d_out, int out_size)
{
    const float* x = (const float*)d_in[0];
    const float* y = (const float*)d_in[1];
    float* out = (float*)d_out;

    static bool attr_set = false;
    if (!attr_set) {
        cudaFuncSetAttribute(corr_mma_kernel,
                             cudaFuncAttributeMaxDynamicSharedMemorySize,
                             SMEM_BYTES);
        attr_set = true;
    }

    corr_mma_kernel<<<B_ * H_ * NWT, NTH, SMEM_BYTES>>>(x, y, out);
}